// round 3
// baseline (speedup 1.0000x reference)
#include <cuda_runtime.h>
#include <cstdint>

#define NTOK  32768
#define HDIM  1024
#define HRDIM 512
#define CDIM  4096

// ---------------- scratch (device globals: allocation-free) ----------------
__device__ float g_h1[(size_t)NTOK * HDIM];    // encoder hidden   [32768,1024]
__device__ float g_z [(size_t)NTOK * HRDIM];   // pre-quant z      [32768, 512]
__device__ float g_h2[(size_t)NTOK * HDIM];    // decoder hidden   [32768,1024]
__device__ int   g_idx[NTOK];                  // argmin indices
__device__ float g_cnorm[CDIM];                // ||e_c||^2
__device__ float g_part[NTOK];                 // per-token (z-q)^2 partial sums

// ---------------- codebook norms ----------------
__global__ void cnorm_kernel(const float* __restrict__ cb)
{
    __shared__ float s[128];
    const int c = blockIdx.x;
    const float* row = cb + (size_t)c * HRDIM;
    float acc = 0.f;
    for (int k = threadIdx.x; k < HRDIM; k += 128) {
        float v = row[k];
        acc += v * v;
    }
    s[threadIdx.x] = acc;
    __syncthreads();
    for (int off = 64; off > 0; off >>= 1) {
        if (threadIdx.x < off) s[threadIdx.x] += s[threadIdx.x + off];
        __syncthreads();
    }
    if (threadIdx.x == 0) g_cnorm[c] = s[0];
}

// ---------------- generic fp32 SGEMM: C = [relu](A[M,K] @ B[K,N] + bias) ----
// BM=BN=128, BK=16, 256 threads, 8x8 per thread.
template <bool RELU>
__global__ __launch_bounds__(256, 2)
void sgemm_kernel(const float* __restrict__ A, const float* __restrict__ B,
                  const float* __restrict__ bias, float* __restrict__ C,
                  int M, int N, int K)
{
    __shared__ float As[16][128];
    __shared__ float Bs[16][128];

    const int tid = threadIdx.x;
    const int tx  = tid & 15;       // 0..15 -> cols
    const int ty  = tid >> 4;       // 0..15 -> rows
    const int m0  = ty * 8;
    const int n0  = tx * 8;
    const int bm  = blockIdx.y * 128;
    const int bn  = blockIdx.x * 128;

    float acc[8][8];
#pragma unroll
    for (int i = 0; i < 8; i++)
#pragma unroll
        for (int j = 0; j < 8; j++) acc[i][j] = 0.f;

    for (int kt = 0; kt < K; kt += 16) {
        // load A tile 128x16 (transpose into As[k][m])
#pragma unroll
        for (int l = 0; l < 2; l++) {
            int t   = tid + l * 256;
            int row = t >> 2;
            int kq  = (t & 3) * 4;
            float4 v = *(const float4*)(A + (size_t)(bm + row) * K + kt + kq);
            As[kq + 0][row] = v.x;
            As[kq + 1][row] = v.y;
            As[kq + 2][row] = v.z;
            As[kq + 3][row] = v.w;
        }
        // load B tile 16x128 (direct)
#pragma unroll
        for (int l = 0; l < 2; l++) {
            int t  = tid + l * 256;
            int kr = t >> 5;
            int nq = (t & 31) * 4;
            float4 v = *(const float4*)(B + (size_t)(kt + kr) * N + bn + nq);
            *(float4*)&Bs[kr][nq] = v;
        }
        __syncthreads();

#pragma unroll
        for (int k = 0; k < 16; k++) {
            float a[8], b[8];
            *(float4*)&a[0] = *(const float4*)&As[k][m0];
            *(float4*)&a[4] = *(const float4*)&As[k][m0 + 4];
            *(float4*)&b[0] = *(const float4*)&Bs[k][n0];
            *(float4*)&b[4] = *(const float4*)&Bs[k][n0 + 4];
#pragma unroll
            for (int i = 0; i < 8; i++)
#pragma unroll
                for (int j = 0; j < 8; j++)
                    acc[i][j] += a[i] * b[j];
        }
        __syncthreads();
    }

    float bb[8];
    *(float4*)&bb[0] = *(const float4*)(bias + bn + n0);
    *(float4*)&bb[4] = *(const float4*)(bias + bn + n0 + 4);

#pragma unroll
    for (int i = 0; i < 8; i++) {
        float o[8];
#pragma unroll
        for (int j = 0; j < 8; j++) {
            float v = acc[i][j] + bb[j];
            if (RELU) v = v > 0.f ? v : 0.f;
            o[j] = v;
        }
        float* dst = C + (size_t)(bm + m0 + i) * N + bn + n0;
        *(float4*)dst       = *(float4*)&o[0];
        *(float4*)(dst + 4) = *(float4*)&o[4];
    }
}

// ---------------- fused distance GEMM + argmin ------------------------------
// For 128 tokens per block: argmin_c ( ||e_c||^2 - 2 z.e_c ) over all 4096 c.
__global__ __launch_bounds__(256, 2)
void dist_argmin_kernel(const float* __restrict__ Z, const float* __restrict__ CB)
{
    __shared__ float As[16][128];
    __shared__ float Bs[16][128];
    __shared__ float rv[128][17];
    __shared__ int   ri[128][17];

    const int tid = threadIdx.x;
    const int tx  = tid & 15;
    const int ty  = tid >> 4;
    const int m0  = ty * 8;
    const int n0  = tx * 8;
    const int bm  = blockIdx.x * 128;

    float minv[8];
    int   mini[8];
#pragma unroll
    for (int i = 0; i < 8; i++) { minv[i] = 3.4e38f; mini[i] = 0; }

    for (int ct = 0; ct < CDIM; ct += 128) {
        float acc[8][8];
#pragma unroll
        for (int i = 0; i < 8; i++)
#pragma unroll
            for (int j = 0; j < 8; j++) acc[i][j] = 0.f;

        for (int kt = 0; kt < HRDIM; kt += 16) {
            // Z tile 128x16 -> As[k][m]
#pragma unroll
            for (int l = 0; l < 2; l++) {
                int t   = tid + l * 256;
                int row = t >> 2;
                int kq  = (t & 3) * 4;
                float4 v = *(const float4*)(Z + (size_t)(bm + row) * HRDIM + kt + kq);
                As[kq + 0][row] = v.x;
                As[kq + 1][row] = v.y;
                As[kq + 2][row] = v.z;
                As[kq + 3][row] = v.w;
            }
            // codebook tile: CB[c, k] row-major [C,HR] -> transpose into Bs[k][c]
#pragma unroll
            for (int l = 0; l < 2; l++) {
                int t  = tid + l * 256;
                int cl = t >> 2;
                int kq = (t & 3) * 4;
                float4 v = *(const float4*)(CB + (size_t)(ct + cl) * HRDIM + kt + kq);
                Bs[kq + 0][cl] = v.x;
                Bs[kq + 1][cl] = v.y;
                Bs[kq + 2][cl] = v.z;
                Bs[kq + 3][cl] = v.w;
            }
            __syncthreads();

#pragma unroll
            for (int k = 0; k < 16; k++) {
                float a[8], b[8];
                *(float4*)&a[0] = *(const float4*)&As[k][m0];
                *(float4*)&a[4] = *(const float4*)&As[k][m0 + 4];
                *(float4*)&b[0] = *(const float4*)&Bs[k][n0];
                *(float4*)&b[4] = *(const float4*)&Bs[k][n0 + 4];
#pragma unroll
                for (int i = 0; i < 8; i++)
#pragma unroll
                    for (int j = 0; j < 8; j++)
                        acc[i][j] += a[i] * b[j];
            }
            __syncthreads();
        }

        // epilogue: score = cnorm[c] - 2*dot; running argmin (c ascending -> ties keep lowest)
        float cn[8];
#pragma unroll
        for (int j = 0; j < 8; j++) cn[j] = g_cnorm[ct + n0 + j];
#pragma unroll
        for (int i = 0; i < 8; i++) {
#pragma unroll
            for (int j = 0; j < 8; j++) {
                float s = cn[j] - 2.f * acc[i][j];
                if (s < minv[i]) { minv[i] = s; mini[i] = ct + n0 + j; }
            }
        }
    }

#pragma unroll
    for (int i = 0; i < 8; i++) {
        rv[m0 + i][tx] = minv[i];
        ri[m0 + i][tx] = mini[i];
    }
    __syncthreads();
    if (tid < 128) {
        float bv = rv[tid][0];
        int   bi = ri[tid][0];
#pragma unroll
        for (int j = 1; j < 16; j++) {
            float v = rv[tid][j];
            int   ii = ri[tid][j];
            if (v < bv || (v == bv && ii < bi)) { bv = v; bi = ii; }
        }
        g_idx[bm + tid] = bi;
    }
}

// ---------------- gather + STE + per-token commit partial + index write -----
__global__ void gather_kernel(const float* __restrict__ CB,
                              float* __restrict__ outq,
                              float* __restrict__ outidx)
{
    __shared__ float s[128];
    const int n = blockIdx.x;
    const int t = threadIdx.x;
    const int id = g_idx[n];

    float4 z4 = *(const float4*)(g_z + (size_t)n * HRDIM + t * 4);
    float4 q4 = *(const float4*)(CB + (size_t)id * HRDIM + t * 4);

    float4 o;
    o.x = z4.x + (q4.x - z4.x);
    o.y = z4.y + (q4.y - z4.y);
    o.z = z4.z + (q4.z - z4.z);
    o.w = z4.w + (q4.w - z4.w);
    *(float4*)(outq + (size_t)n * HRDIM + t * 4) = o;

    float dx = z4.x - q4.x, dy = z4.y - q4.y, dz = z4.z - q4.z, dw = z4.w - q4.w;
    s[t] = dx * dx + dy * dy + dz * dz + dw * dw;
    __syncthreads();
    for (int off = 64; off > 0; off >>= 1) {
        if (t < off) s[t] += s[t + off];
        __syncthreads();
    }
    if (t == 0) {
        g_part[n] = s[0];
        outidx[n] = (float)id;
    }
}

// ---------------- deterministic commit-loss sum ----------------
__global__ void losssum_kernel(float* __restrict__ outloss)
{
    __shared__ float s[1024];
    float acc = 0.f;
    for (int i = threadIdx.x; i < NTOK; i += 1024) acc += g_part[i];
    s[threadIdx.x] = acc;
    __syncthreads();
    for (int off = 512; off > 0; off >>= 1) {
        if (threadIdx.x < off) s[threadIdx.x] += s[threadIdx.x + off];
        __syncthreads();
    }
    if (threadIdx.x == 0)
        outloss[0] = 0.25f * s[0] / (float)((size_t)NTOK * HRDIM);
}

// ---------------- launch ----------------
extern "C" void kernel_launch(void* const* d_in, const int* in_sizes, int n_in,
                              void* d_out, int out_size)
{
    const float* x   = (const float*)d_in[0];
    const float* ew1 = (const float*)d_in[1];
    const float* eb1 = (const float*)d_in[2];
    const float* ew2 = (const float*)d_in[3];
    const float* eb2 = (const float*)d_in[4];
    const float* cb  = (const float*)d_in[5];
    const float* dw1 = (const float*)d_in[6];
    const float* db1 = (const float*)d_in[7];
    const float* dw2 = (const float*)d_in[8];
    const float* db2 = (const float*)d_in[9];

    float* out       = (float*)d_out;
    float* out_recon = out;                                          // [32768,1024]
    float* out_q     = out + (size_t)NTOK * HDIM;                    // [32768, 512]
    float* out_idx   = out_q + (size_t)NTOK * HRDIM;                 // [32768]
    float* out_loss  = out_idx + NTOK;                               // [1]

    float *h1, *z, *h2;
    cudaGetSymbolAddress((void**)&h1, g_h1);
    cudaGetSymbolAddress((void**)&z,  g_z);
    cudaGetSymbolAddress((void**)&h2, g_h2);

    // codebook squared norms
    cnorm_kernel<<<CDIM, 128>>>(cb);

    // encoder: h1 = relu(x @ ew1 + eb1)
    sgemm_kernel<true><<<dim3(HDIM / 128, NTOK / 128), 256>>>(x, ew1, eb1, h1, NTOK, HDIM, HDIM);
    // z = h1 @ ew2 + eb2
    sgemm_kernel<false><<<dim3(HRDIM / 128, NTOK / 128), 256>>>(h1, ew2, eb2, z, NTOK, HRDIM, HDIM);

    // nearest codebook entry per token
    dist_argmin_kernel<<<NTOK / 128, 256>>>(z, cb);

    // quantized_st + commit partials + indices
    gather_kernel<<<NTOK, 128>>>(cb, out_q, out_idx);
    losssum_kernel<<<1, 1024>>>(out_loss);

    // decoder: h2 = relu(q_st @ dw1 + db1); recon = h2 @ dw2 + db2
    sgemm_kernel<true><<<dim3(HDIM / 128, NTOK / 128), 256>>>(out_q, dw1, db1, h2, NTOK, HDIM, HRDIM);
    sgemm_kernel<false><<<dim3(HDIM / 128, NTOK / 128), 256>>>(h2, dw2, db2, out_recon, NTOK, HDIM, HDIM);
}

// round 7
// speedup vs baseline: 1.0337x; 1.0337x over previous
#include <cuda_runtime.h>
#include <cstdint>

#define NTOK  32768
#define HDIM  1024
#define HRDIM 512
#define CDIM  4096

// packed 2xfp32 FMA (Blackwell f32x2; ptxas never emits this from C++)
#define FMA2(d, a, b, c) \
    asm("fma.rn.f32x2 %0, %1, %2, %3;" : "=l"(d) : "l"(a), "l"(b), "l"(c))
#define SPLAT2(d, s) \
    asm("mov.b64 %0, {%1, %1};" : "=l"(d) : "r"(s))
#define UNPK2(lo, hi, s) \
    asm("mov.b64 {%0, %1}, %2;" : "=r"(lo), "=r"(hi) : "l"(s))

// ---------------- scratch (device globals: allocation-free) ----------------
__device__ float g_h1[(size_t)NTOK * HDIM];    // encoder hidden   [32768,1024]
__device__ float g_z [(size_t)NTOK * HRDIM];   // pre-quant z      [32768, 512]
__device__ float g_h2[(size_t)NTOK * HDIM];    // decoder hidden   [32768,1024]
__device__ int   g_idx[NTOK];                  // argmin indices
__device__ float g_cnorm[CDIM];                // ||e_c||^2
__device__ float g_part[NTOK];                 // per-token (z-q)^2 partial sums

// ---------------- codebook norms ----------------
__global__ void cnorm_kernel(const float* __restrict__ cb)
{
    __shared__ float s[128];
    const int c = blockIdx.x;
    const float* row = cb + (size_t)c * HRDIM;
    float acc = 0.f;
    for (int k = threadIdx.x; k < HRDIM; k += 128) {
        float v = row[k];
        acc += v * v;
    }
    s[threadIdx.x] = acc;
    __syncthreads();
    for (int off = 64; off > 0; off >>= 1) {
        if (threadIdx.x < off) s[threadIdx.x] += s[threadIdx.x + off];
        __syncthreads();
    }
    if (threadIdx.x == 0) g_cnorm[c] = s[0];
}

// ---------------- generic fp32 SGEMM via FFMA2 ------------------------------
// C = [relu](A[M,K] @ B[K,N] + bias). BM=BN=128, BK=16, 256 threads, 8x8/thr.
template <bool RELU>
__global__ __launch_bounds__(256, 2)
void sgemm_kernel(const float* __restrict__ A, const float* __restrict__ B,
                  const float* __restrict__ bias, float* __restrict__ C,
                  int M, int N, int K)
{
    __shared__ float As[16][128];
    __shared__ float Bs[16][128];

    const int tid = threadIdx.x;
    const int tx  = tid & 15;       // 0..15 -> cols
    const int ty  = tid >> 4;       // 0..15 -> rows
    const int m0  = ty * 8;
    const int n0  = tx * 8;
    const int bm  = blockIdx.y * 128;
    const int bn  = blockIdx.x * 128;

    unsigned long long acc[8][4];   // 8 rows x 4 column-pairs (f32x2)
#pragma unroll
    for (int i = 0; i < 8; i++)
#pragma unroll
        for (int j = 0; j < 4; j++) acc[i][j] = 0ULL;

    for (int kt = 0; kt < K; kt += 16) {
        // load A tile 128x16 (transpose into As[k][m])
#pragma unroll
        for (int l = 0; l < 2; l++) {
            int t   = tid + l * 256;
            int row = t >> 2;
            int kq  = (t & 3) * 4;
            float4 v = *(const float4*)(A + (size_t)(bm + row) * K + kt + kq);
            As[kq + 0][row] = v.x;
            As[kq + 1][row] = v.y;
            As[kq + 2][row] = v.z;
            As[kq + 3][row] = v.w;
        }
        // load B tile 16x128 (direct)
#pragma unroll
        for (int l = 0; l < 2; l++) {
            int t  = tid + l * 256;
            int kr = t >> 5;
            int nq = (t & 31) * 4;
            float4 v = *(const float4*)(B + (size_t)(kt + kr) * N + bn + nq);
            *(float4*)&Bs[kr][nq] = v;
        }
        __syncthreads();

#pragma unroll
        for (int k = 0; k < 16; k++) {
            float4 a0 = *(const float4*)&As[k][m0];
            float4 a1 = *(const float4*)&As[k][m0 + 4];
            ulonglong2 bb0 = *(const ulonglong2*)&Bs[k][n0];
            ulonglong2 bb1 = *(const ulonglong2*)&Bs[k][n0 + 4];
            unsigned long long b2[4] = { bb0.x, bb0.y, bb1.x, bb1.y };
            unsigned long long a2[8];
            SPLAT2(a2[0], __float_as_uint(a0.x));
            SPLAT2(a2[1], __float_as_uint(a0.y));
            SPLAT2(a2[2], __float_as_uint(a0.z));
            SPLAT2(a2[3], __float_as_uint(a0.w));
            SPLAT2(a2[4], __float_as_uint(a1.x));
            SPLAT2(a2[5], __float_as_uint(a1.y));
            SPLAT2(a2[6], __float_as_uint(a1.z));
            SPLAT2(a2[7], __float_as_uint(a1.w));
#pragma unroll
            for (int i = 0; i < 8; i++)
#pragma unroll
                for (int j = 0; j < 4; j++)
                    FMA2(acc[i][j], a2[i], b2[j], acc[i][j]);
        }
        __syncthreads();
    }

    float bb[8];
    *(float4*)&bb[0] = *(const float4*)(bias + bn + n0);
    *(float4*)&bb[4] = *(const float4*)(bias + bn + n0 + 4);

#pragma unroll
    for (int i = 0; i < 8; i++) {
        float o[8];
#pragma unroll
        for (int j = 0; j < 4; j++) {
            unsigned int lo, hi;
            UNPK2(lo, hi, acc[i][j]);
            o[2 * j]     = __uint_as_float(lo);
            o[2 * j + 1] = __uint_as_float(hi);
        }
#pragma unroll
        for (int j = 0; j < 8; j++) {
            float v = o[j] + bb[j];
            if (RELU) v = v > 0.f ? v : 0.f;
            o[j] = v;
        }
        float* dst = C + (size_t)(bm + m0 + i) * N + bn + n0;
        *(float4*)dst       = *(float4*)&o[0];
        *(float4*)(dst + 4) = *(float4*)&o[4];
    }
}

// ---------------- fused distance GEMM + argmin (FFMA2) ----------------------
// For 128 tokens per block: argmin_c ( ||e_c||^2 - 2 z.e_c ) over all 4096 c.
__global__ __launch_bounds__(256, 2)
void dist_argmin_kernel(const float* __restrict__ Z, const float* __restrict__ CB)
{
    __shared__ float As[16][128];
    __shared__ float Bs[16][128];
    __shared__ float rv[128][17];
    __shared__ int   ri[128][17];

    const int tid = threadIdx.x;
    const int tx  = tid & 15;
    const int ty  = tid >> 4;
    const int m0  = ty * 8;
    const int n0  = tx * 8;
    const int bm  = blockIdx.x * 128;

    float minv[8];
    int   mini[8];
#pragma unroll
    for (int i = 0; i < 8; i++) { minv[i] = 3.4e38f; mini[i] = 0; }

    for (int ct = 0; ct < CDIM; ct += 128) {
        unsigned long long acc[8][4];
#pragma unroll
        for (int i = 0; i < 8; i++)
#pragma unroll
            for (int j = 0; j < 4; j++) acc[i][j] = 0ULL;

        for (int kt = 0; kt < HRDIM; kt += 16) {
            // Z tile 128x16 -> As[k][m]
#pragma unroll
            for (int l = 0; l < 2; l++) {
                int t   = tid + l * 256;
                int row = t >> 2;
                int kq  = (t & 3) * 4;
                float4 v = *(const float4*)(Z + (size_t)(bm + row) * HRDIM + kt + kq);
                As[kq + 0][row] = v.x;
                As[kq + 1][row] = v.y;
                As[kq + 2][row] = v.z;
                As[kq + 3][row] = v.w;
            }
            // codebook tile: CB[c, k] row-major [C,HR] -> transpose into Bs[k][c]
#pragma unroll
            for (int l = 0; l < 2; l++) {
                int t  = tid + l * 256;
                int cl = t >> 2;
                int kq = (t & 3) * 4;
                float4 v = *(const float4*)(CB + (size_t)(ct + cl) * HRDIM + kt + kq);
                Bs[kq + 0][cl] = v.x;
                Bs[kq + 1][cl] = v.y;
                Bs[kq + 2][cl] = v.z;
                Bs[kq + 3][cl] = v.w;
            }
            __syncthreads();

#pragma unroll
            for (int k = 0; k < 16; k++) {
                float4 a0 = *(const float4*)&As[k][m0];
                float4 a1 = *(const float4*)&As[k][m0 + 4];
                ulonglong2 bb0 = *(const ulonglong2*)&Bs[k][n0];
                ulonglong2 bb1 = *(const ulonglong2*)&Bs[k][n0 + 4];
                unsigned long long b2[4] = { bb0.x, bb0.y, bb1.x, bb1.y };
                unsigned long long a2[8];
                SPLAT2(a2[0], __float_as_uint(a0.x));
                SPLAT2(a2[1], __float_as_uint(a0.y));
                SPLAT2(a2[2], __float_as_uint(a0.z));
                SPLAT2(a2[3], __float_as_uint(a0.w));
                SPLAT2(a2[4], __float_as_uint(a1.x));
                SPLAT2(a2[5], __float_as_uint(a1.y));
                SPLAT2(a2[6], __float_as_uint(a1.z));
                SPLAT2(a2[7], __float_as_uint(a1.w));
#pragma unroll
                for (int i = 0; i < 8; i++)
#pragma unroll
                    for (int j = 0; j < 4; j++)
                        FMA2(acc[i][j], a2[i], b2[j], acc[i][j]);
            }
            __syncthreads();
        }

        // epilogue: score = cnorm[c] - 2*dot; running argmin (c ascending -> ties keep lowest)
        float cn[8];
#pragma unroll
        for (int j = 0; j < 8; j++) cn[j] = g_cnorm[ct + n0 + j];
#pragma unroll
        for (int i = 0; i < 8; i++) {
#pragma unroll
            for (int j = 0; j < 4; j++) {
                unsigned int lo, hi;
                UNPK2(lo, hi, acc[i][j]);
                float s0 = cn[2 * j]     - 2.f * __uint_as_float(lo);
                float s1 = cn[2 * j + 1] - 2.f * __uint_as_float(hi);
                if (s0 < minv[i]) { minv[i] = s0; mini[i] = ct + n0 + 2 * j; }
                if (s1 < minv[i]) { minv[i] = s1; mini[i] = ct + n0 + 2 * j + 1; }
            }
        }
    }

#pragma unroll
    for (int i = 0; i < 8; i++) {
        rv[m0 + i][tx] = minv[i];
        ri[m0 + i][tx] = mini[i];
    }
    __syncthreads();
    if (tid < 128) {
        float bv = rv[tid][0];
        int   bi = ri[tid][0];
#pragma unroll
        for (int j = 1; j < 16; j++) {
            float v = rv[tid][j];
            int   ii = ri[tid][j];
            if (v < bv || (v == bv && ii < bi)) { bv = v; bi = ii; }
        }
        g_idx[bm + tid] = bi;
    }
}

// ---------------- gather + STE + per-token commit partial + index write -----
__global__ void gather_kernel(const float* __restrict__ CB,
                              float* __restrict__ outq,
                              float* __restrict__ outidx)
{
    __shared__ float s[128];
    const int n = blockIdx.x;
    const int t = threadIdx.x;
    const int id = g_idx[n];

    float4 z4 = *(const float4*)(g_z + (size_t)n * HRDIM + t * 4);
    float4 q4 = *(const float4*)(CB + (size_t)id * HRDIM + t * 4);

    float4 o;
    o.x = z4.x + (q4.x - z4.x);
    o.y = z4.y + (q4.y - z4.y);
    o.z = z4.z + (q4.z - z4.z);
    o.w = z4.w + (q4.w - z4.w);
    *(float4*)(outq + (size_t)n * HRDIM + t * 4) = o;

    float dx = z4.x - q4.x, dy = z4.y - q4.y, dz = z4.z - q4.z, dw = z4.w - q4.w;
    s[t] = dx * dx + dy * dy + dz * dz + dw * dw;
    __syncthreads();
    for (int off = 64; off > 0; off >>= 1) {
        if (t < off) s[t] += s[t + off];
        __syncthreads();
    }
    if (t == 0) {
        g_part[n] = s[0];
        outidx[n] = (float)id;
    }
}

// ---------------- deterministic commit-loss sum ----------------
__global__ void losssum_kernel(float* __restrict__ outloss)
{
    __shared__ float s[1024];
    float acc = 0.f;
    for (int i = threadIdx.x; i < NTOK; i += 1024) acc += g_part[i];
    s[threadIdx.x] = acc;
    __syncthreads();
    for (int off = 512; off > 0; off >>= 1) {
        if (threadIdx.x < off) s[threadIdx.x] += s[threadIdx.x + off];
        __syncthreads();
    }
    if (threadIdx.x == 0)
        outloss[0] = 0.25f * s[0] / (float)((size_t)NTOK * HRDIM);
}

// ---------------- launch ----------------
extern "C" void kernel_launch(void* const* d_in, const int* in_sizes, int n_in,
                              void* d_out, int out_size)
{
    const float* x   = (const float*)d_in[0];
    const float* ew1 = (const float*)d_in[1];
    const float* eb1 = (const float*)d_in[2];
    const float* ew2 = (const float*)d_in[3];
    const float* eb2 = (const float*)d_in[4];
    const float* cb  = (const float*)d_in[5];
    const float* dw1 = (const float*)d_in[6];
    const float* db1 = (const float*)d_in[7];
    const float* dw2 = (const float*)d_in[8];
    const float* db2 = (const float*)d_in[9];

    float* out       = (float*)d_out;
    float* out_recon = out;                                          // [32768,1024]
    float* out_q     = out + (size_t)NTOK * HDIM;                    // [32768, 512]
    float* out_idx   = out_q + (size_t)NTOK * HRDIM;                 // [32768]
    float* out_loss  = out_idx + NTOK;                               // [1]

    float *h1, *z, *h2;
    cudaGetSymbolAddress((void**)&h1, g_h1);
    cudaGetSymbolAddress((void**)&z,  g_z);
    cudaGetSymbolAddress((void**)&h2, g_h2);

    // codebook squared norms
    cnorm_kernel<<<CDIM, 128>>>(cb);

    // encoder: h1 = relu(x @ ew1 + eb1)
    sgemm_kernel<true><<<dim3(HDIM / 128, NTOK / 128), 256>>>(x, ew1, eb1, h1, NTOK, HDIM, HDIM);
    // z = h1 @ ew2 + eb2
    sgemm_kernel<false><<<dim3(HRDIM / 128, NTOK / 128), 256>>>(h1, ew2, eb2, z, NTOK, HRDIM, HDIM);

    // nearest codebook entry per token
    dist_argmin_kernel<<<NTOK / 128, 256>>>(z, cb);

    // quantized_st + commit partials + indices
    gather_kernel<<<NTOK, 128>>>(cb, out_q, out_idx);
    losssum_kernel<<<1, 1024>>>(out_loss);

    // decoder: h2 = relu(q_st @ dw1 + db1); recon = h2 @ dw2 + db2
    sgemm_kernel<true><<<dim3(HDIM / 128, NTOK / 128), 256>>>(out_q, dw1, db1, h2, NTOK, HDIM, HRDIM);
    sgemm_kernel<false><<<dim3(HDIM / 128, NTOK / 128), 256>>>(h2, dw2, db2, out_recon, NTOK, HDIM, HDIM);
}

// round 8
// speedup vs baseline: 1.0347x; 1.0009x over previous
#include <cuda_runtime.h>
#include <cstdint>

#define NTOK  32768
#define HDIM  1024
#define HRDIM 512
#define CDIM  4096

// packed 2xfp32 FMA (Blackwell f32x2; ptxas never emits this from C++)
#define FMA2(d, a, b, c) \
    asm("fma.rn.f32x2 %0, %1, %2, %3;" : "=l"(d) : "l"(a), "l"(b), "l"(c))
#define SPLAT2(d, s) \
    asm("mov.b64 %0, {%1, %1};" : "=l"(d) : "r"(s))
#define UNPK2(lo, hi, s) \
    asm("mov.b64 {%0, %1}, %2;" : "=r"(lo), "=r"(hi) : "l"(s))

// ---------------- scratch (device globals: allocation-free) ----------------
__device__ float g_h1[(size_t)NTOK * HDIM];    // encoder hidden   [32768,1024]
__device__ float g_z [(size_t)NTOK * HRDIM];   // pre-quant z      [32768, 512]
__device__ float g_h2[(size_t)NTOK * HDIM];    // decoder hidden   [32768,1024]
__device__ int   g_idx[NTOK];                  // argmin indices
__device__ float g_cnorm[CDIM];                // ||e_c||^2
__device__ float g_part[NTOK];                 // per-token (z-q)^2 partial sums

// ---------------- codebook norms ----------------
__global__ void cnorm_kernel(const float* __restrict__ cb)
{
    __shared__ float s[128];
    const int c = blockIdx.x;
    const float* row = cb + (size_t)c * HRDIM;
    float acc = 0.f;
    for (int k = threadIdx.x; k < HRDIM; k += 128) {
        float v = row[k];
        acc += v * v;
    }
    s[threadIdx.x] = acc;
    __syncthreads();
    for (int off = 64; off > 0; off >>= 1) {
        if (threadIdx.x < off) s[threadIdx.x] += s[threadIdx.x + off];
        __syncthreads();
    }
    if (threadIdx.x == 0) g_cnorm[c] = s[0];
}

// ---------------- generic fp32 SGEMM via FFMA2 ------------------------------
// C = [relu](A[M,K] @ B[K,N] + bias). BM=BN=128, BK=16, 256 threads, 8x8/thr.
template <bool RELU>
__global__ __launch_bounds__(256, 2)
void sgemm_kernel(const float* __restrict__ A, const float* __restrict__ B,
                  const float* __restrict__ bias, float* __restrict__ C,
                  int M, int N, int K)
{
    __shared__ float As[16][128];
    __shared__ float Bs[16][128];

    const int tid = threadIdx.x;
    const int tx  = tid & 15;       // 0..15 -> cols
    const int ty  = tid >> 4;       // 0..15 -> rows
    const int m0  = ty * 8;
    const int n0  = tx * 8;
    const int bm  = blockIdx.y * 128;
    const int bn  = blockIdx.x * 128;

    unsigned long long acc[8][4];   // 8 rows x 4 column-pairs (f32x2)
#pragma unroll
    for (int i = 0; i < 8; i++)
#pragma unroll
        for (int j = 0; j < 4; j++) acc[i][j] = 0ULL;

    for (int kt = 0; kt < K; kt += 16) {
        // load A tile 128x16 (transpose into As[k][m])
#pragma unroll
        for (int l = 0; l < 2; l++) {
            int t   = tid + l * 256;
            int row = t >> 2;
            int kq  = (t & 3) * 4;
            float4 v = *(const float4*)(A + (size_t)(bm + row) * K + kt + kq);
            As[kq + 0][row] = v.x;
            As[kq + 1][row] = v.y;
            As[kq + 2][row] = v.z;
            As[kq + 3][row] = v.w;
        }
        // load B tile 16x128 (direct)
#pragma unroll
        for (int l = 0; l < 2; l++) {
            int t  = tid + l * 256;
            int kr = t >> 5;
            int nq = (t & 31) * 4;
            float4 v = *(const float4*)(B + (size_t)(kt + kr) * N + bn + nq);
            *(float4*)&Bs[kr][nq] = v;
        }
        __syncthreads();

#pragma unroll
        for (int k = 0; k < 16; k++) {
            float4 a0 = *(const float4*)&As[k][m0];
            float4 a1 = *(const float4*)&As[k][m0 + 4];
            ulonglong2 bb0 = *(const ulonglong2*)&Bs[k][n0];
            ulonglong2 bb1 = *(const ulonglong2*)&Bs[k][n0 + 4];
            unsigned long long b2[4] = { bb0.x, bb0.y, bb1.x, bb1.y };
            unsigned long long a2[8];
            SPLAT2(a2[0], __float_as_uint(a0.x));
            SPLAT2(a2[1], __float_as_uint(a0.y));
            SPLAT2(a2[2], __float_as_uint(a0.z));
            SPLAT2(a2[3], __float_as_uint(a0.w));
            SPLAT2(a2[4], __float_as_uint(a1.x));
            SPLAT2(a2[5], __float_as_uint(a1.y));
            SPLAT2(a2[6], __float_as_uint(a1.z));
            SPLAT2(a2[7], __float_as_uint(a1.w));
#pragma unroll
            for (int i = 0; i < 8; i++)
#pragma unroll
                for (int j = 0; j < 4; j++)
                    FMA2(acc[i][j], a2[i], b2[j], acc[i][j]);
        }
        __syncthreads();
    }

    float bb[8];
    *(float4*)&bb[0] = *(const float4*)(bias + bn + n0);
    *(float4*)&bb[4] = *(const float4*)(bias + bn + n0 + 4);

#pragma unroll
    for (int i = 0; i < 8; i++) {
        float o[8];
#pragma unroll
        for (int j = 0; j < 4; j++) {
            unsigned int lo, hi;
            UNPK2(lo, hi, acc[i][j]);
            o[2 * j]     = __uint_as_float(lo);
            o[2 * j + 1] = __uint_as_float(hi);
        }
#pragma unroll
        for (int j = 0; j < 8; j++) {
            float v = o[j] + bb[j];
            if (RELU) v = v > 0.f ? v : 0.f;
            o[j] = v;
        }
        float* dst = C + (size_t)(bm + m0 + i) * N + bn + n0;
        *(float4*)dst       = *(float4*)&o[0];
        *(float4*)(dst + 4) = *(float4*)&o[4];
    }
}

// ---------------- fused distance GEMM + argmin (FFMA2) ----------------------
// For 128 tokens per block: argmin_c ( ||e_c||^2 - 2 z.e_c ) over all 4096 c.
__global__ __launch_bounds__(256, 2)
void dist_argmin_kernel(const float* __restrict__ Z, const float* __restrict__ CB)
{
    __shared__ float As[16][128];
    __shared__ float Bs[16][128];
    __shared__ float rv[128][17];
    __shared__ int   ri[128][17];

    const int tid = threadIdx.x;
    const int tx  = tid & 15;
    const int ty  = tid >> 4;
    const int m0  = ty * 8;
    const int n0  = tx * 8;
    const int bm  = blockIdx.x * 128;

    float minv[8];
    int   mini[8];
#pragma unroll
    for (int i = 0; i < 8; i++) { minv[i] = 3.4e38f; mini[i] = 0; }

    for (int ct = 0; ct < CDIM; ct += 128) {
        unsigned long long acc[8][4];
#pragma unroll
        for (int i = 0; i < 8; i++)
#pragma unroll
            for (int j = 0; j < 4; j++) acc[i][j] = 0ULL;

        for (int kt = 0; kt < HRDIM; kt += 16) {
            // Z tile 128x16 -> As[k][m]
#pragma unroll
            for (int l = 0; l < 2; l++) {
                int t   = tid + l * 256;
                int row = t >> 2;
                int kq  = (t & 3) * 4;
                float4 v = *(const float4*)(Z + (size_t)(bm + row) * HRDIM + kt + kq);
                As[kq + 0][row] = v.x;
                As[kq + 1][row] = v.y;
                As[kq + 2][row] = v.z;
                As[kq + 3][row] = v.w;
            }
            // codebook tile: CB[c, k] row-major [C,HR] -> transpose into Bs[k][c]
#pragma unroll
            for (int l = 0; l < 2; l++) {
                int t  = tid + l * 256;
                int cl = t >> 2;
                int kq = (t & 3) * 4;
                float4 v = *(const float4*)(CB + (size_t)(ct + cl) * HRDIM + kt + kq);
                Bs[kq + 0][cl] = v.x;
                Bs[kq + 1][cl] = v.y;
                Bs[kq + 2][cl] = v.z;
                Bs[kq + 3][cl] = v.w;
            }
            __syncthreads();

#pragma unroll
            for (int k = 0; k < 16; k++) {
                float4 a0 = *(const float4*)&As[k][m0];
                float4 a1 = *(const float4*)&As[k][m0 + 4];
                ulonglong2 bb0 = *(const ulonglong2*)&Bs[k][n0];
                ulonglong2 bb1 = *(const ulonglong2*)&Bs[k][n0 + 4];
                unsigned long long b2[4] = { bb0.x, bb0.y, bb1.x, bb1.y };
                unsigned long long a2[8];
                SPLAT2(a2[0], __float_as_uint(a0.x));
                SPLAT2(a2[1], __float_as_uint(a0.y));
                SPLAT2(a2[2], __float_as_uint(a0.z));
                SPLAT2(a2[3], __float_as_uint(a0.w));
                SPLAT2(a2[4], __float_as_uint(a1.x));
                SPLAT2(a2[5], __float_as_uint(a1.y));
                SPLAT2(a2[6], __float_as_uint(a1.z));
                SPLAT2(a2[7], __float_as_uint(a1.w));
#pragma unroll
                for (int i = 0; i < 8; i++)
#pragma unroll
                    for (int j = 0; j < 4; j++)
                        FMA2(acc[i][j], a2[i], b2[j], acc[i][j]);
            }
            __syncthreads();
        }

        // epilogue: score = cnorm[c] - 2*dot; running argmin (c ascending -> ties keep lowest)
        float cn[8];
#pragma unroll
        for (int j = 0; j < 8; j++) cn[j] = g_cnorm[ct + n0 + j];
#pragma unroll
        for (int i = 0; i < 8; i++) {
#pragma unroll
            for (int j = 0; j < 4; j++) {
                unsigned int lo, hi;
                UNPK2(lo, hi, acc[i][j]);
                float s0 = cn[2 * j]     - 2.f * __uint_as_float(lo);
                float s1 = cn[2 * j + 1] - 2.f * __uint_as_float(hi);
                if (s0 < minv[i]) { minv[i] = s0; mini[i] = ct + n0 + 2 * j; }
                if (s1 < minv[i]) { minv[i] = s1; mini[i] = ct + n0 + 2 * j + 1; }
            }
        }
    }

#pragma unroll
    for (int i = 0; i < 8; i++) {
        rv[m0 + i][tx] = minv[i];
        ri[m0 + i][tx] = mini[i];
    }
    __syncthreads();
    if (tid < 128) {
        float bv = rv[tid][0];
        int   bi = ri[tid][0];
#pragma unroll
        for (int j = 1; j < 16; j++) {
            float v = rv[tid][j];
            int   ii = ri[tid][j];
            if (v < bv || (v == bv && ii < bi)) { bv = v; bi = ii; }
        }
        g_idx[bm + tid] = bi;
    }
}

// ---------------- gather + STE + per-token commit partial + index write -----
__global__ void gather_kernel(const float* __restrict__ CB,
                              float* __restrict__ outq,
                              float* __restrict__ outidx)
{
    __shared__ float s[128];
    const int n = blockIdx.x;
    const int t = threadIdx.x;
    const int id = g_idx[n];

    float4 z4 = *(const float4*)(g_z + (size_t)n * HRDIM + t * 4);
    float4 q4 = *(const float4*)(CB + (size_t)id * HRDIM + t * 4);

    float4 o;
    o.x = z4.x + (q4.x - z4.x);
    o.y = z4.y + (q4.y - z4.y);
    o.z = z4.z + (q4.z - z4.z);
    o.w = z4.w + (q4.w - z4.w);
    *(float4*)(outq + (size_t)n * HRDIM + t * 4) = o;

    float dx = z4.x - q4.x, dy = z4.y - q4.y, dz = z4.z - q4.z, dw = z4.w - q4.w;
    s[t] = dx * dx + dy * dy + dz * dz + dw * dw;
    __syncthreads();
    for (int off = 64; off > 0; off >>= 1) {
        if (t < off) s[t] += s[t + off];
        __syncthreads();
    }
    if (t == 0) {
        g_part[n] = s[0];
        outidx[n] = (float)id;
    }
}

// ---------------- deterministic commit-loss sum ----------------
__global__ void losssum_kernel(float* __restrict__ outloss)
{
    __shared__ float s[1024];
    float acc = 0.f;
    for (int i = threadIdx.x; i < NTOK; i += 1024) acc += g_part[i];
    s[threadIdx.x] = acc;
    __syncthreads();
    for (int off = 512; off > 0; off >>= 1) {
        if (threadIdx.x < off) s[threadIdx.x] += s[threadIdx.x + off];
        __syncthreads();
    }
    if (threadIdx.x == 0)
        outloss[0] = 0.25f * s[0] / (float)((size_t)NTOK * HRDIM);
}

// ---------------- launch ----------------
extern "C" void kernel_launch(void* const* d_in, const int* in_sizes, int n_in,
                              void* d_out, int out_size)
{
    const float* x   = (const float*)d_in[0];
    const float* ew1 = (const float*)d_in[1];
    const float* eb1 = (const float*)d_in[2];
    const float* ew2 = (const float*)d_in[3];
    const float* eb2 = (const float*)d_in[4];
    const float* cb  = (const float*)d_in[5];
    const float* dw1 = (const float*)d_in[6];
    const float* db1 = (const float*)d_in[7];
    const float* dw2 = (const float*)d_in[8];
    const float* db2 = (const float*)d_in[9];

    float* out       = (float*)d_out;
    float* out_recon = out;                                          // [32768,1024]
    float* out_q     = out + (size_t)NTOK * HDIM;                    // [32768, 512]
    float* out_idx   = out_q + (size_t)NTOK * HRDIM;                 // [32768]
    float* out_loss  = out_idx + NTOK;                               // [1]

    float *h1, *z, *h2;
    cudaGetSymbolAddress((void**)&h1, g_h1);
    cudaGetSymbolAddress((void**)&z,  g_z);
    cudaGetSymbolAddress((void**)&h2, g_h2);

    // codebook squared norms
    cnorm_kernel<<<CDIM, 128>>>(cb);

    // encoder: h1 = relu(x @ ew1 + eb1)
    sgemm_kernel<true><<<dim3(HDIM / 128, NTOK / 128), 256>>>(x, ew1, eb1, h1, NTOK, HDIM, HDIM);
    // z = h1 @ ew2 + eb2
    sgemm_kernel<false><<<dim3(HRDIM / 128, NTOK / 128), 256>>>(h1, ew2, eb2, z, NTOK, HRDIM, HDIM);

    // nearest codebook entry per token
    dist_argmin_kernel<<<NTOK / 128, 256>>>(z, cb);

    // quantized_st + commit partials + indices
    gather_kernel<<<NTOK, 128>>>(cb, out_q, out_idx);
    losssum_kernel<<<1, 1024>>>(out_loss);

    // decoder: h2 = relu(q_st @ dw1 + db1); recon = h2 @ dw2 + db2
    sgemm_kernel<true><<<dim3(HDIM / 128, NTOK / 128), 256>>>(out_q, dw1, db1, h2, NTOK, HDIM, HRDIM);
    sgemm_kernel<false><<<dim3(HDIM / 128, NTOK / 128), 256>>>(h2, dw2, db2, out_recon, NTOK, HDIM, HDIM);
}

// round 10
// speedup vs baseline: 1.3338x; 1.2891x over previous
#include <cuda_runtime.h>
#include <cuda_bf16.h>
#include <cstdint>

#define NTOK  32768
#define HDIM  1024
#define HRDIM 512
#define CDIM  4096
#define NSTRIP (CDIM / 128)

// Stage layout: A limbs 3 x 16KB (256x32 bf16), B limbs 3 x 8KB (128x32 bf16)
#define A_LIMB 16384
#define B_LIMB 8192
#define B_OFF  49152            // 3 * A_LIMB
#define STAGE  73728            // B_OFF + 3 * B_LIMB
#define SMEM_BYTES (2 * STAGE)  // 147456

// ---------------- scratch (device globals: allocation-free) ----------------
__device__ float g_h1[(size_t)NTOK * HDIM];
__device__ float g_z [(size_t)NTOK * HRDIM];
__device__ float g_h2[(size_t)NTOK * HDIM];
__device__ float g_wt[3 * 1024 * 1024];
__device__ int   g_idx[NTOK];
__device__ float g_cnorm[CDIM];
__device__ float g_part[NTOK];
__device__ float g_pval[(size_t)NTOK * NSTRIP];
__device__ int   g_pidx[(size_t)NTOK * NSTRIP];

// ===================== PTX primitives (plain sm_80+ ISA) ====================
__device__ __forceinline__ uint32_t smem_to_u32(const void* p) {
    uint32_t a;
    asm("{ .reg .u64 t; cvta.to.shared.u64 t, %1; cvt.u32.u64 %0, t; }" : "=r"(a) : "l"(p));
    return a;
}
__device__ __forceinline__ void ldm4(uint32_t* r, uint32_t addr) {
    asm volatile("ldmatrix.sync.aligned.m8n8.x4.shared.b16 {%0,%1,%2,%3}, [%4];"
                 : "=r"(r[0]), "=r"(r[1]), "=r"(r[2]), "=r"(r[3]) : "r"(addr));
}
__device__ __forceinline__ void mma16816(float* c, const uint32_t* a, const uint32_t* b) {
    asm volatile("mma.sync.aligned.m16n8k16.row.col.f32.bf16.bf16.f32 "
                 "{%0,%1,%2,%3},{%4,%5,%6,%7},{%8,%9},{%0,%1,%2,%3};"
                 : "+f"(c[0]), "+f"(c[1]), "+f"(c[2]), "+f"(c[3])
                 : "r"(a[0]), "r"(a[1]), "r"(a[2]), "r"(a[3]), "r"(b[0]), "r"(b[1]));
}

// swizzle: 16B chunk permute within 64B rows, conflict-free for ldmatrix + STS.128
__device__ __forceinline__ uint32_t swz(int row, int ch) {
    return (uint32_t)(row * 64 + ((ch ^ ((row >> 1) & 3)) << 4));
}

__device__ __forceinline__ void ldg16(float* v, const float* p) {
#pragma unroll
    for (int i = 0; i < 4; i++) *(float4*)(v + 4 * i) = *(const float4*)(p + 4 * i);
}

// split 16 fp32 -> bf16 limbs (exact 3-limb decomposition), store swizzled
template <int NL>
__device__ __forceinline__ void split_store16(const float* v, char* base, int row, int half, int limb_sz) {
    uint32_t hr[8], mr[8], lr[8];
#pragma unroll
    for (int i = 0; i < 8; i++) {
        float a0 = v[2 * i], a1 = v[2 * i + 1];
        float h0 = __bfloat162float(__float2bfloat16(a0));
        float h1 = __bfloat162float(__float2bfloat16(a1));
        float r0 = a0 - h0, r1 = a1 - h1;
        float m0 = __bfloat162float(__float2bfloat16(r0));
        float m1 = __bfloat162float(__float2bfloat16(r1));
        float l0 = r0 - m0, l1 = r1 - m1;
        asm("cvt.rn.bf16x2.f32 %0, %1, %2;" : "=r"(hr[i]) : "f"(h1), "f"(h0));
        asm("cvt.rn.bf16x2.f32 %0, %1, %2;" : "=r"(mr[i]) : "f"(m1), "f"(m0));
        if (NL == 3)
            asm("cvt.rn.bf16x2.f32 %0, %1, %2;" : "=r"(lr[i]) : "f"(l1), "f"(l0));
    }
#pragma unroll
    for (int c = 0; c < 2; c++) {
        uint32_t off = swz(row, 2 * half + c);
        *(uint4*)(base + off)            = make_uint4(hr[c*4], hr[c*4+1], hr[c*4+2], hr[c*4+3]);
        *(uint4*)(base + limb_sz + off)  = make_uint4(mr[c*4], mr[c*4+1], mr[c*4+2], mr[c*4+3]);
        if (NL == 3)
            *(uint4*)(base + 2*limb_sz + off) = make_uint4(lr[c*4], lr[c*4+1], lr[c*4+2], lr[c*4+3]);
    }
}

// one BK=32 stage of limb-pass MMAs
template <int NPASS>
__device__ __forceinline__ void compute_stage(uint32_t ss, int lane, int wm, int wn, float acc[4][8][4]) {
    const int pa[6] = {0, 0, 1, 1, 0, 2};
    const int pb[6] = {0, 1, 0, 1, 2, 0};
    const int arow_off = lane & 15;
    const int achk_off = lane >> 4;
    const int brow_off = (lane & 7) + ((lane >> 4) << 3);
    const int bchk_off = (lane >> 3) & 1;
#pragma unroll
    for (int p = 0; p < NPASS; p++) {
        uint32_t ab = ss + pa[p] * A_LIMB;
        uint32_t bb = ss + B_OFF + pb[p] * B_LIMB;
#pragma unroll
        for (int ks = 0; ks < 2; ks++) {
            uint32_t af[4][4], bf[4][4];
#pragma unroll
            for (int mt = 0; mt < 4; mt++) {
                int row = wm * 64 + mt * 16 + arow_off;
                ldm4(af[mt], ab + swz(row, ks * 2 + achk_off));
            }
#pragma unroll
            for (int np = 0; np < 4; np++) {
                int row = wn * 64 + np * 16 + brow_off;
                ldm4(bf[np], bb + swz(row, ks * 2 + bchk_off));
            }
#pragma unroll
            for (int mt = 0; mt < 4; mt++)
#pragma unroll
                for (int nt = 0; nt < 8; nt++)
                    mma16816(acc[mt][nt], af[mt], &bf[nt >> 1][(nt & 1) * 2]);
        }
    }
}

// mainloop: C_acc = A[bm:bm+256, :K] * B[bn:bn+128, :K]^T, limb-emulated fp32
template <int K, int NPASS>
__device__ __forceinline__ void run_mainloop(
    const float* __restrict__ A, const float* __restrict__ B,
    int bm, int bn, char* sm, float acc[4][8][4])
{
    constexpr int NKT = K / 32;
    constexpr int NL  = (NPASS >= 6) ? 3 : 2;
    const int tid  = threadIdx.x;
    const int lane = tid & 31, warp = tid >> 5;
    const int wm = warp >> 1, wn = warp & 1;
    const uint32_t sb = smem_to_u32(sm);

    const int ar = tid >> 1, ah = tid & 1;   // A rows ar, ar+128, half ah
    const int br = tid >> 1, bh = tid & 1;   // B row br, half bh

#pragma unroll
    for (int mt = 0; mt < 4; mt++)
#pragma unroll
        for (int nt = 0; nt < 8; nt++)
#pragma unroll
            for (int q = 0; q < 4; q++) acc[mt][nt][q] = 0.f;

    {   // prologue: stage 0
        float v[16];
        ldg16(v, A + (size_t)(bm + ar) * K + ah * 16);
        split_store16<NL>(v, sm, ar, ah, A_LIMB);
        ldg16(v, A + (size_t)(bm + ar + 128) * K + ah * 16);
        split_store16<NL>(v, sm, ar + 128, ah, A_LIMB);
        ldg16(v, B + (size_t)(bn + br) * K + bh * 16);
        split_store16<NL>(v, sm + B_OFF, br, bh, B_LIMB);
    }
    __syncthreads();

    for (int t = 0; t < NKT; t++) {
        float va0[16], va1[16], vb[16];
        const bool pf = (t + 1 < NKT);
        if (pf) {
            const int k0 = (t + 1) * 32;
            ldg16(va0, A + (size_t)(bm + ar) * K + k0 + ah * 16);
            ldg16(va1, A + (size_t)(bm + ar + 128) * K + k0 + ah * 16);
            ldg16(vb,  B + (size_t)(bn + br) * K + k0 + bh * 16);
        }
        compute_stage<NPASS>(sb + (uint32_t)(t & 1) * STAGE, lane, wm, wn, acc);
        if (pf) {
            char* st = sm + ((t + 1) & 1) * STAGE;
            split_store16<NL>(va0, st, ar, ah, A_LIMB);
            split_store16<NL>(va1, st, ar + 128, ah, A_LIMB);
            split_store16<NL>(vb,  st + B_OFF, br, bh, B_LIMB);
        }
        __syncthreads();
    }
}

// ---------------- dense GEMM: C = [relu](A @ B^T + bias) --------------------
template <int K, int NPASS, bool RELU>
__global__ __launch_bounds__(256, 1)
void tgemm_kernel(const float* __restrict__ A, const float* __restrict__ B,
                  const float* __restrict__ bias, float* __restrict__ C, int N)
{
    extern __shared__ char sm[];
    float acc[4][8][4];
    const int bm = blockIdx.y * 256, bn = blockIdx.x * 128;
    run_mainloop<K, NPASS>(A, B, bm, bn, sm, acc);

    const int tid = threadIdx.x, lane = tid & 31, warp = tid >> 5;
    const int wm = warp >> 1, wn = warp & 1;
#pragma unroll
    for (int mt = 0; mt < 4; mt++) {
        const int r0 = bm + wm * 64 + mt * 16 + (lane >> 2);
#pragma unroll
        for (int nt = 0; nt < 8; nt++) {
            const int c0 = bn + wn * 64 + nt * 8 + (lane & 3) * 2;
            const float b0 = bias[c0], b1 = bias[c0 + 1];
            float2 lo = { acc[mt][nt][0] + b0, acc[mt][nt][1] + b1 };
            float2 hi = { acc[mt][nt][2] + b0, acc[mt][nt][3] + b1 };
            if (RELU) {
                lo.x = lo.x > 0.f ? lo.x : 0.f;  lo.y = lo.y > 0.f ? lo.y : 0.f;
                hi.x = hi.x > 0.f ? hi.x : 0.f;  hi.y = hi.y > 0.f ? hi.y : 0.f;
            }
            *(float2*)(C + (size_t)r0 * N + c0)       = lo;
            *(float2*)(C + (size_t)(r0 + 8) * N + c0) = hi;
        }
    }
}

// ---------------- distance + partial argmin per (token-tile, strip) ---------
__global__ __launch_bounds__(256, 1)
void tdist_kernel(const float* __restrict__ Z, const float* __restrict__ CB)
{
    extern __shared__ char sm[];
    float acc[4][8][4];
    const int strip = blockIdx.x;
    const int bn = strip * 128, bm = blockIdx.y * 256;
    run_mainloop<HRDIM, 6>(Z, CB, bm, bn, sm, acc);

    const int tid = threadIdx.x, lane = tid & 31, warp = tid >> 5;
    const int wm = warp >> 1, wn = warp & 1;

    float bv[8];
    int   bi[8];
#pragma unroll
    for (int s = 0; s < 8; s++) { bv[s] = 3.4e38f; bi[s] = 0; }

#pragma unroll
    for (int mt = 0; mt < 4; mt++) {
#pragma unroll
        for (int nt = 0; nt < 8; nt++) {
            const int c0 = bn + wn * 64 + nt * 8 + (lane & 3) * 2;
            const float cn0 = g_cnorm[c0], cn1 = g_cnorm[c0 + 1];
            const float s0 = cn0 - 2.f * acc[mt][nt][0];
            const float s1 = cn1 - 2.f * acc[mt][nt][1];
            const float s2 = cn0 - 2.f * acc[mt][nt][2];
            const float s3 = cn1 - 2.f * acc[mt][nt][3];
            if (s0 < bv[2*mt])   { bv[2*mt]   = s0; bi[2*mt]   = c0; }
            if (s1 < bv[2*mt])   { bv[2*mt]   = s1; bi[2*mt]   = c0 + 1; }
            if (s2 < bv[2*mt+1]) { bv[2*mt+1] = s2; bi[2*mt+1] = c0; }
            if (s3 < bv[2*mt+1]) { bv[2*mt+1] = s3; bi[2*mt+1] = c0 + 1; }
        }
    }
    // reduce across the 4 lanes sharing the same rows (lane>>2 invariant)
#pragma unroll
    for (int s = 0; s < 8; s++) {
#pragma unroll
        for (int d = 1; d < 4; d <<= 1) {
            float ov = __shfl_xor_sync(0xffffffffu, bv[s], d);
            int   oi = __shfl_xor_sync(0xffffffffu, bi[s], d);
            if (ov < bv[s] || (ov == bv[s] && oi < bi[s])) { bv[s] = ov; bi[s] = oi; }
        }
    }
    float* sval = (float*)sm;            // 2 x 256 floats
    int*   sidx = (int*)(sm + 2048);     // 2 x 256 ints
    if ((lane & 3) == 0) {
        const int q = lane >> 2;
#pragma unroll
        for (int mt = 0; mt < 4; mt++) {
            const int r = wm * 64 + mt * 16 + q;
            sval[wn * 256 + r]     = bv[2*mt];   sidx[wn * 256 + r]     = bi[2*mt];
            sval[wn * 256 + r + 8] = bv[2*mt+1]; sidx[wn * 256 + r + 8] = bi[2*mt+1];
        }
    }
    __syncthreads();
    {
        float v0 = sval[tid];       int i0 = sidx[tid];
        const float v1 = sval[256 + tid];
        const int   i1 = sidx[256 + tid];
        if (v1 < v0 || (v1 == v0 && i1 < i0)) { v0 = v1; i0 = i1; }
        const int tok = bm + tid;
        g_pval[(size_t)tok * NSTRIP + strip] = v0;
        g_pidx[(size_t)tok * NSTRIP + strip] = i0;
    }
}

// ---------------- strip combine -------------------------------------------
__global__ void combine_kernel()
{
    const int tok = blockIdx.x * 256 + threadIdx.x;
    const float* pv = g_pval + (size_t)tok * NSTRIP;
    const int*   pi = g_pidx + (size_t)tok * NSTRIP;
    float best = pv[0];
    int   bi   = pi[0];
#pragma unroll
    for (int s = 1; s < NSTRIP; s++) {
        const float v = pv[s];
        if (v < best) { best = v; bi = pi[s]; }
    }
    g_idx[tok] = bi;
}

// ---------------- weight transpose: out[N][K] = in[K][N] --------------------
__global__ void transpose_kernel(const float* __restrict__ in, float* __restrict__ out,
                                 int K, int N)
{
    __shared__ float t[32][33];
    const int n0 = blockIdx.x * 32, k0 = blockIdx.y * 32;
    const int tx = threadIdx.x, ty = threadIdx.y;
#pragma unroll
    for (int i = 0; i < 4; i++)
        t[ty + i * 8][tx] = in[(size_t)(k0 + ty + i * 8) * N + n0 + tx];
    __syncthreads();
#pragma unroll
    for (int i = 0; i < 4; i++)
        out[(size_t)(n0 + ty + i * 8) * K + k0 + tx] = t[tx][ty + i * 8];
}

// ---------------- codebook norms -------------------------------------------
__global__ void cnorm_kernel(const float* __restrict__ cb)
{
    __shared__ float s[128];
    const int c = blockIdx.x;
    const float* row = cb + (size_t)c * HRDIM;
    float acc = 0.f;
    for (int k = threadIdx.x; k < HRDIM; k += 128) {
        float v = row[k];
        acc += v * v;
    }
    s[threadIdx.x] = acc;
    __syncthreads();
    for (int off = 64; off > 0; off >>= 1) {
        if (threadIdx.x < off) s[threadIdx.x] += s[threadIdx.x + off];
        __syncthreads();
    }
    if (threadIdx.x == 0) g_cnorm[c] = s[0];
}

// ---------------- gather + STE + commit partials + index write --------------
__global__ void gather_kernel(const float* __restrict__ CB,
                              float* __restrict__ outq,
                              float* __restrict__ outidx)
{
    __shared__ float s[128];
    const int n = blockIdx.x;
    const int t = threadIdx.x;
    const int id = g_idx[n];

    float4 z4 = *(const float4*)(g_z + (size_t)n * HRDIM + t * 4);
    float4 q4 = *(const float4*)(CB + (size_t)id * HRDIM + t * 4);

    float4 o;
    o.x = z4.x + (q4.x - z4.x);
    o.y = z4.y + (q4.y - z4.y);
    o.z = z4.z + (q4.z - z4.z);
    o.w = z4.w + (q4.w - z4.w);
    *(float4*)(outq + (size_t)n * HRDIM + t * 4) = o;

    float dx = z4.x - q4.x, dy = z4.y - q4.y, dz = z4.z - q4.z, dw = z4.w - q4.w;
    s[t] = dx * dx + dy * dy + dz * dz + dw * dw;
    __syncthreads();
    for (int off = 64; off > 0; off >>= 1) {
        if (t < off) s[t] += s[t + off];
        __syncthreads();
    }
    if (t == 0) {
        g_part[n] = s[0];
        outidx[n] = (float)id;
    }
}

// ---------------- deterministic commit-loss sum -----------------------------
__global__ void losssum_kernel(float* __restrict__ outloss)
{
    __shared__ float s[1024];
    float acc = 0.f;
    for (int i = threadIdx.x; i < NTOK; i += 1024) acc += g_part[i];
    s[threadIdx.x] = acc;
    __syncthreads();
    for (int off = 512; off > 0; off >>= 1) {
        if (threadIdx.x < off) s[threadIdx.x] += s[threadIdx.x + off];
        __syncthreads();
    }
    if (threadIdx.x == 0)
        outloss[0] = 0.25f * s[0] / (float)((size_t)NTOK * HRDIM);
}

// ---------------- launch ----------------------------------------------------
extern "C" void kernel_launch(void* const* d_in, const int* in_sizes, int n_in,
                              void* d_out, int out_size)
{
    const float* x   = (const float*)d_in[0];
    const float* ew1 = (const float*)d_in[1];
    const float* eb1 = (const float*)d_in[2];
    const float* ew2 = (const float*)d_in[3];
    const float* eb2 = (const float*)d_in[4];
    const float* cb  = (const float*)d_in[5];
    const float* dw1 = (const float*)d_in[6];
    const float* db1 = (const float*)d_in[7];
    const float* dw2 = (const float*)d_in[8];
    const float* db2 = (const float*)d_in[9];

    float* out       = (float*)d_out;
    float* out_recon = out;
    float* out_q     = out + (size_t)NTOK * HDIM;
    float* out_idx   = out_q + (size_t)NTOK * HRDIM;
    float* out_loss  = out_idx + NTOK;

    float *h1, *z, *h2, *wt;
    cudaGetSymbolAddress((void**)&h1, g_h1);
    cudaGetSymbolAddress((void**)&z,  g_z);
    cudaGetSymbolAddress((void**)&h2, g_h2);
    cudaGetSymbolAddress((void**)&wt, g_wt);
    float* wt1 = wt;                       // ew1^T [1024,1024]
    float* wt2 = wt + 1024 * 1024;         // ew2^T [512,1024]
    float* wt3 = wt + 1536 * 1024;         // dw1^T [1024,512]
    float* wt4 = wt + 2048 * 1024;         // dw2^T [1024,1024]

    cudaFuncSetAttribute(tgemm_kernel<1024, 6, true>,  cudaFuncAttributeMaxDynamicSharedMemorySize, SMEM_BYTES);
    cudaFuncSetAttribute(tgemm_kernel<1024, 6, false>, cudaFuncAttributeMaxDynamicSharedMemorySize, SMEM_BYTES);
    cudaFuncSetAttribute(tgemm_kernel<512, 3, true>,   cudaFuncAttributeMaxDynamicSharedMemorySize, SMEM_BYTES);
    cudaFuncSetAttribute(tgemm_kernel<1024, 3, false>, cudaFuncAttributeMaxDynamicSharedMemorySize, SMEM_BYTES);
    cudaFuncSetAttribute(tdist_kernel,                 cudaFuncAttributeMaxDynamicSharedMemorySize, SMEM_BYTES);

    cnorm_kernel<<<CDIM, 128>>>(cb);
    dim3 tb(32, 8);
    transpose_kernel<<<dim3(1024 / 32, 1024 / 32), tb>>>(ew1, wt1, 1024, 1024);
    transpose_kernel<<<dim3(512 / 32, 1024 / 32),  tb>>>(ew2, wt2, 1024, 512);
    transpose_kernel<<<dim3(1024 / 32, 512 / 32),  tb>>>(dw1, wt3, 512, 1024);
    transpose_kernel<<<dim3(1024 / 32, 1024 / 32), tb>>>(dw2, wt4, 1024, 1024);

    // encoder (6-pass emulated fp32 on bf16 HMMA)
    tgemm_kernel<1024, 6, true><<<dim3(8, NTOK / 256), 256, SMEM_BYTES>>>(x, wt1, eb1, h1, HDIM);
    tgemm_kernel<1024, 6, false><<<dim3(4, NTOK / 256), 256, SMEM_BYTES>>>(h1, wt2, eb2, z, HRDIM);

    // nearest codebook entry (6-pass) + combine
    tdist_kernel<<<dim3(NSTRIP, NTOK / 256), 256, SMEM_BYTES>>>(z, cb);
    combine_kernel<<<NTOK / 256, 256>>>();

    // quantized_st + commit partials + indices + loss
    gather_kernel<<<NTOK, 128>>>(cb, out_q, out_idx);
    losssum_kernel<<<1, 1024>>>(out_loss);

    // decoder (3-pass)
    tgemm_kernel<512, 3, true><<<dim3(8, NTOK / 256), 256, SMEM_BYTES>>>(out_q, wt3, db1, h2, HDIM);
    tgemm_kernel<1024, 3, false><<<dim3(8, NTOK / 256), 256, SMEM_BYTES>>>(h2, wt4, db2, out_recon, HDIM);
}

// round 11
// speedup vs baseline: 2.0345x; 1.5253x over previous
#include <cuda_runtime.h>
#include <cuda_bf16.h>
#include <cstdint>

#define NTOK  32768
#define HDIM  1024
#define HRDIM 512
#define CDIM  4096
#define NSTRIP (CDIM / 128)

// Stage: A limbs 3 x 16KB (256x32 bf16) | B limbs 3 x 8KB (128x32 bf16)
#define A_LIMB 16384
#define B_LIMB 8192
#define B_OFF  49152
#define STAGE  73728
#define SMEM_BYTES (3 * STAGE)   // 221184: 3-deep cp.async ring

using bf16 = __nv_bfloat16;

// ---------------- global limb planes + scratch (allocation-free) ------------
__device__ bf16 g_xh[(size_t)NTOK * HDIM],  g_xm[(size_t)NTOK * HDIM],  g_xl[(size_t)NTOK * HDIM];
__device__ bf16 g_h1h[(size_t)NTOK * HDIM], g_h1m[(size_t)NTOK * HDIM], g_h1l[(size_t)NTOK * HDIM];
__device__ bf16 g_zh[(size_t)NTOK * HRDIM], g_zm[(size_t)NTOK * HRDIM], g_zl[(size_t)NTOK * HRDIM];
__device__ bf16 g_qh[(size_t)NTOK * HRDIM], g_qm[(size_t)NTOK * HRDIM];
__device__ bf16 g_h2h[(size_t)NTOK * HDIM], g_h2m[(size_t)NTOK * HDIM];
__device__ bf16 g_cbh[(size_t)CDIM * HRDIM], g_cbm[(size_t)CDIM * HRDIM], g_cbl[(size_t)CDIM * HRDIM];
__device__ bf16 g_w1h[1024 * 1024], g_w1m[1024 * 1024], g_w1l[1024 * 1024];
__device__ bf16 g_w2h[512 * 1024],  g_w2m[512 * 1024],  g_w2l[512 * 1024];
__device__ bf16 g_w3h[1024 * 512],  g_w3m[1024 * 512];
__device__ bf16 g_w4h[1024 * 1024], g_w4m[1024 * 1024];
__device__ float g_z[(size_t)NTOK * HRDIM];
__device__ int   g_idx[NTOK];
__device__ float g_cnorm[CDIM];
__device__ float g_part[NTOK];
__device__ float g_pval[(size_t)NTOK * NSTRIP];
__device__ int   g_pidx[(size_t)NTOK * NSTRIP];

// ===================== PTX primitives =======================================
__device__ __forceinline__ uint32_t smem_to_u32(const void* p) {
    uint32_t a;
    asm("{ .reg .u64 t; cvta.to.shared.u64 t, %1; cvt.u32.u64 %0, t; }" : "=r"(a) : "l"(p));
    return a;
}
__device__ __forceinline__ void ldm4(uint32_t* r, uint32_t addr) {
    asm volatile("ldmatrix.sync.aligned.m8n8.x4.shared.b16 {%0,%1,%2,%3}, [%4];"
                 : "=r"(r[0]), "=r"(r[1]), "=r"(r[2]), "=r"(r[3]) : "r"(addr));
}
__device__ __forceinline__ void mma16816(float* c, const uint32_t* a, const uint32_t* b) {
    asm volatile("mma.sync.aligned.m16n8k16.row.col.f32.bf16.bf16.f32 "
                 "{%0,%1,%2,%3},{%4,%5,%6,%7},{%8,%9},{%0,%1,%2,%3};"
                 : "+f"(c[0]), "+f"(c[1]), "+f"(c[2]), "+f"(c[3])
                 : "r"(a[0]), "r"(a[1]), "r"(a[2]), "r"(a[3]), "r"(b[0]), "r"(b[1]));
}
__device__ __forceinline__ void cp16(uint32_t dst, const void* src) {
    asm volatile("cp.async.cg.shared.global [%0], [%1], 16;" :: "r"(dst), "l"(src) : "memory");
}
#define CP_COMMIT() asm volatile("cp.async.commit_group;" ::: "memory")
#define CP_WAIT1()  asm volatile("cp.async.wait_group 1;" ::: "memory")

// swizzle: 16B chunk permute within 64B rows (4 chunks/row)
__device__ __forceinline__ uint32_t swz(int row, int ch) {
    return (uint32_t)(row * 64 + ((ch ^ ((row >> 1) & 3)) << 4));
}

__device__ __forceinline__ uint32_t pack_bf16x2(float lo, float hi) {
    uint32_t p;
    asm("cvt.rn.bf16x2.f32 %0, %1, %2;" : "=r"(p) : "f"(hi), "f"(lo));
    return p;
}
// exact 3-limb split of a pair, packed bf16x2 per limb
__device__ __forceinline__ void split_pair(float a, float b,
                                           uint32_t& hp, uint32_t& mp, uint32_t& lp) {
    float ha = __bfloat162float(__float2bfloat16(a));
    float hb = __bfloat162float(__float2bfloat16(b));
    float ra = a - ha, rb = b - hb;
    float ma = __bfloat162float(__float2bfloat16(ra));
    float mb = __bfloat162float(__float2bfloat16(rb));
    float la = ra - ma, lb = rb - mb;
    hp = pack_bf16x2(ha, hb);
    mp = pack_bf16x2(ma, mb);
    lp = pack_bf16x2(la, lb);
}

// ---------------- stage loader: cp.async bf16 limb tiles --------------------
template <int NL>
__device__ __forceinline__ void issue_stage(
    const bf16* a0, const bf16* a1, const bf16* a2,
    const bf16* b0, const bf16* b1, const bf16* b2,
    int lda, int ldb, int bm, int bn, int k0, uint32_t ss, int tid)
{
    const bf16* ap[3] = { a0, a1, a2 };
    const bf16* bp[3] = { b0, b1, b2 };
#pragma unroll
    for (int i = 0; i < NL * 4; i++) {           // A: NL*1024 16B chunks
        const int id = tid + i * 256;
        const int la = i >> 2;                   // constant per i
        const int rem = id & 1023;
        const int row = rem >> 2, ch = rem & 3;
        const char* g = (const char*)(ap[la] + (size_t)(bm + row) * lda + k0) + ch * 16;
        cp16(ss + la * A_LIMB + swz(row, ch), g);
    }
#pragma unroll
    for (int i = 0; i < NL * 2; i++) {           // B: NL*512 16B chunks
        const int id = tid + i * 256;
        const int lb = i >> 1;
        const int rem = id & 511;
        const int row = rem >> 2, ch = rem & 3;
        const char* g = (const char*)(bp[lb] + (size_t)(bn + row) * ldb + k0) + ch * 16;
        cp16(ss + B_OFF + lb * B_LIMB + swz(row, ch), g);
    }
}

// ---------------- one BK=32 stage: B-limb-resident limb-pass MMAs -----------
template <int NPASS>
__device__ __forceinline__ void compute_stage(uint32_t ss, int lane, int wm, int wn,
                                              float acc[4][8][4])
{
    constexpr int NLB = (NPASS == 6) ? 3 : 2;
    constexpr int NLA = (NPASS == 6) ? 3 : 2;
    const int arow = lane & 15, ach = lane >> 4;
    const int brow = (lane & 7) + ((lane >> 4) << 3), bch = (lane >> 3) & 1;
#pragma unroll
    for (int ks = 0; ks < 2; ks++) {
        uint32_t bf[3][4][4];
#pragma unroll
        for (int lb = 0; lb < NLB; lb++) {
            const uint32_t bb = ss + B_OFF + lb * B_LIMB;
#pragma unroll
            for (int np = 0; np < 4; np++)
                ldm4(bf[lb][np], bb + swz(wn * 64 + np * 16 + brow, ks * 2 + bch));
        }
#pragma unroll
        for (int la = 0; la < NLA; la++) {
            uint32_t af[4][4];
            const uint32_t ab = ss + la * A_LIMB;
#pragma unroll
            for (int mt = 0; mt < 4; mt++)
                ldm4(af[mt], ab + swz(wm * 64 + mt * 16 + arow, ks * 2 + ach));
            const int lbmax = (NPASS == 6) ? (3 - la) : (la == 0 ? 2 : 1);
#pragma unroll
            for (int lb = 0; lb < 3; lb++) {
                if (lb >= lbmax) break;
#pragma unroll
                for (int mt = 0; mt < 4; mt++)
#pragma unroll
                    for (int nt = 0; nt < 8; nt++)
                        mma16816(acc[mt][nt], af[mt], &bf[lb][nt >> 1][(nt & 1) * 2]);
            }
        }
    }
}

// ---------------- mainloop: 3-stage cp.async ring ---------------------------
template <int K, int NPASS>
__device__ __forceinline__ void run_mainloop(
    const bf16* a0, const bf16* a1, const bf16* a2,
    const bf16* b0, const bf16* b1, const bf16* b2,
    int bm, int bn, char* sm, float acc[4][8][4])
{
    constexpr int NKT = K / 32;
    constexpr int NL  = (NPASS == 6) ? 3 : 2;
    const int tid = threadIdx.x, lane = tid & 31, warp = tid >> 5;
    const int wm = warp >> 1, wn = warp & 1;
    const uint32_t sb = smem_to_u32(sm);

#pragma unroll
    for (int mt = 0; mt < 4; mt++)
#pragma unroll
        for (int nt = 0; nt < 8; nt++)
#pragma unroll
            for (int q = 0; q < 4; q++) acc[mt][nt][q] = 0.f;

    issue_stage<NL>(a0, a1, a2, b0, b1, b2, K, K, bm, bn, 0,  sb,         tid);
    CP_COMMIT();
    issue_stage<NL>(a0, a1, a2, b0, b1, b2, K, K, bm, bn, 32, sb + STAGE, tid);
    CP_COMMIT();

    int sc = 0, si = 2;
    for (int t = 0; t < NKT; t++) {
        CP_WAIT1();
        __syncthreads();
        if (t + 2 < NKT)
            issue_stage<NL>(a0, a1, a2, b0, b1, b2, K, K, bm, bn, (t + 2) * 32,
                            sb + si * STAGE, tid);
        CP_COMMIT();
        compute_stage<NPASS>(sb + sc * STAGE, lane, wm, wn, acc);
        sc = (sc + 1 == 3) ? 0 : sc + 1;
        si = (si + 1 == 3) ? 0 : si + 1;
    }
}

// ---------------- dense GEMM: [relu](A@B^T+bias) -> fp32 and/or limb planes -
template <int K, int NPASS, bool RELU, bool WF32, int NLOUT>
__global__ __launch_bounds__(256, 1)
void tgemm_kernel(const bf16* a0, const bf16* a1, const bf16* a2,
                  const bf16* b0, const bf16* b1, const bf16* b2,
                  const float* __restrict__ bias, float* __restrict__ Cf,
                  bf16* __restrict__ Ch, bf16* __restrict__ Cm, bf16* __restrict__ Cl,
                  int N)
{
    extern __shared__ char sm[];
    float acc[4][8][4];
    const int bm = blockIdx.y * 256, bn = blockIdx.x * 128;
    run_mainloop<K, NPASS>(a0, a1, a2, b0, b1, b2, bm, bn, sm, acc);

    const int tid = threadIdx.x, lane = tid & 31, warp = tid >> 5;
    const int wm = warp >> 1, wn = warp & 1;
#pragma unroll
    for (int mt = 0; mt < 4; mt++) {
        const int r0 = bm + wm * 64 + mt * 16 + (lane >> 2);
#pragma unroll
        for (int nt = 0; nt < 8; nt++) {
            const int c0 = bn + wn * 64 + nt * 8 + (lane & 3) * 2;
            const float bb0 = bias[c0], bb1 = bias[c0 + 1];
            float v00 = acc[mt][nt][0] + bb0, v01 = acc[mt][nt][1] + bb1;
            float v10 = acc[mt][nt][2] + bb0, v11 = acc[mt][nt][3] + bb1;
            if (RELU) {
                v00 = v00 > 0.f ? v00 : 0.f;  v01 = v01 > 0.f ? v01 : 0.f;
                v10 = v10 > 0.f ? v10 : 0.f;  v11 = v11 > 0.f ? v11 : 0.f;
            }
            if (WF32) {
                *(float2*)(Cf + (size_t)r0 * N + c0)       = make_float2(v00, v01);
                *(float2*)(Cf + (size_t)(r0 + 8) * N + c0) = make_float2(v10, v11);
            }
            if (NLOUT >= 2) {
                uint32_t h0, m0, l0, h1, m1, l1;
                split_pair(v00, v01, h0, m0, l0);
                split_pair(v10, v11, h1, m1, l1);
                *(uint32_t*)(Ch + (size_t)r0 * N + c0)       = h0;
                *(uint32_t*)(Ch + (size_t)(r0 + 8) * N + c0) = h1;
                *(uint32_t*)(Cm + (size_t)r0 * N + c0)       = m0;
                *(uint32_t*)(Cm + (size_t)(r0 + 8) * N + c0) = m1;
                if (NLOUT == 3) {
                    *(uint32_t*)(Cl + (size_t)r0 * N + c0)       = l0;
                    *(uint32_t*)(Cl + (size_t)(r0 + 8) * N + c0) = l1;
                }
            }
        }
    }
}

// ---------------- distance + partial argmin per (token-tile, strip) ---------
__global__ __launch_bounds__(256, 1)
void tdist_kernel(const bf16* a0, const bf16* a1, const bf16* a2,
                  const bf16* b0, const bf16* b1, const bf16* b2)
{
    extern __shared__ char sm[];
    float acc[4][8][4];
    const int strip = blockIdx.x;
    const int bn = strip * 128, bm = blockIdx.y * 256;
    run_mainloop<HRDIM, 6>(a0, a1, a2, b0, b1, b2, bm, bn, sm, acc);

    const int tid = threadIdx.x, lane = tid & 31, warp = tid >> 5;
    const int wm = warp >> 1, wn = warp & 1;

    float bv[8];
    int   bi[8];
#pragma unroll
    for (int s = 0; s < 8; s++) { bv[s] = 3.4e38f; bi[s] = 0; }

#pragma unroll
    for (int mt = 0; mt < 4; mt++) {
#pragma unroll
        for (int nt = 0; nt < 8; nt++) {
            const int c0 = bn + wn * 64 + nt * 8 + (lane & 3) * 2;
            const float cn0 = g_cnorm[c0], cn1 = g_cnorm[c0 + 1];
            const float s0 = cn0 - 2.f * acc[mt][nt][0];
            const float s1 = cn1 - 2.f * acc[mt][nt][1];
            const float s2 = cn0 - 2.f * acc[mt][nt][2];
            const float s3 = cn1 - 2.f * acc[mt][nt][3];
            if (s0 < bv[2*mt])   { bv[2*mt]   = s0; bi[2*mt]   = c0; }
            if (s1 < bv[2*mt])   { bv[2*mt]   = s1; bi[2*mt]   = c0 + 1; }
            if (s2 < bv[2*mt+1]) { bv[2*mt+1] = s2; bi[2*mt+1] = c0; }
            if (s3 < bv[2*mt+1]) { bv[2*mt+1] = s3; bi[2*mt+1] = c0 + 1; }
        }
    }
#pragma unroll
    for (int s = 0; s < 8; s++) {
#pragma unroll
        for (int d = 1; d < 4; d <<= 1) {
            float ov = __shfl_xor_sync(0xffffffffu, bv[s], d);
            int   oi = __shfl_xor_sync(0xffffffffu, bi[s], d);
            if (ov < bv[s] || (ov == bv[s] && oi < bi[s])) { bv[s] = ov; bi[s] = oi; }
        }
    }
    __syncthreads();                      // all warps done reading ring smem
    float* sval = (float*)sm;
    int*   sidx = (int*)(sm + 2048);
    if ((lane & 3) == 0) {
        const int q = lane >> 2;
#pragma unroll
        for (int mt = 0; mt < 4; mt++) {
            const int r = wm * 64 + mt * 16 + q;
            sval[wn * 256 + r]     = bv[2*mt];   sidx[wn * 256 + r]     = bi[2*mt];
            sval[wn * 256 + r + 8] = bv[2*mt+1]; sidx[wn * 256 + r + 8] = bi[2*mt+1];
        }
    }
    __syncthreads();
    {
        float v0 = sval[tid];       int i0 = sidx[tid];
        const float v1 = sval[256 + tid];
        const int   i1 = sidx[256 + tid];
        if (v1 < v0 || (v1 == v0 && i1 < i0)) { v0 = v1; i0 = i1; }
        const int tok = bm + tid;
        g_pval[(size_t)tok * NSTRIP + strip] = v0;
        g_pidx[(size_t)tok * NSTRIP + strip] = i0;
    }
}

// ---------------- strip combine ---------------------------------------------
__global__ void combine_kernel()
{
    const int tok = blockIdx.x * 256 + threadIdx.x;
    const float* pv = g_pval + (size_t)tok * NSTRIP;
    const int*   pi = g_pidx + (size_t)tok * NSTRIP;
    float best = pv[0];
    int   bi   = pi[0];
#pragma unroll
    for (int s = 1; s < NSTRIP; s++) {
        const float v = pv[s];
        if (v < best) { best = v; bi = pi[s]; }
    }
    g_idx[tok] = bi;
}

// ---------------- input split: x -> 3 limb planes ---------------------------
__global__ void splitx_kernel(const float4* __restrict__ in,
                              uint2* __restrict__ h, uint2* __restrict__ m,
                              uint2* __restrict__ l)
{
    const size_t i = (size_t)blockIdx.x * 256 + threadIdx.x;
    const float4 v = in[i];
    uint32_t h0, m0, l0, h1, m1, l1;
    split_pair(v.x, v.y, h0, m0, l0);
    split_pair(v.z, v.w, h1, m1, l1);
    h[i] = make_uint2(h0, h1);
    m[i] = make_uint2(m0, m1);
    l[i] = make_uint2(l0, l1);
}

// ---------------- codebook: norms + 3 limb planes ---------------------------
__global__ void cbprep_kernel(const float* __restrict__ cb,
                              uint2* __restrict__ h, uint2* __restrict__ m,
                              uint2* __restrict__ l)
{
    __shared__ float s[128];
    const int c = blockIdx.x, t = threadIdx.x;
    const float4 v = ((const float4*)(cb + (size_t)c * HRDIM))[t];
    uint32_t h0, m0, l0, h1, m1, l1;
    split_pair(v.x, v.y, h0, m0, l0);
    split_pair(v.z, v.w, h1, m1, l1);
    const size_t o = (size_t)c * (HRDIM / 4) + t;
    h[o] = make_uint2(h0, h1);
    m[o] = make_uint2(m0, m1);
    l[o] = make_uint2(l0, l1);
    s[t] = v.x * v.x + v.y * v.y + v.z * v.z + v.w * v.w;
    __syncthreads();
    for (int off = 64; off > 0; off >>= 1) {
        if (t < off) s[t] += s[t + off];
        __syncthreads();
    }
    if (t == 0) g_cnorm[c] = s[0];
}

// ---------------- weights: transpose + split to limb planes -----------------
template <int NL>
__global__ void transsplit_kernel(const float* __restrict__ in,
                                  bf16* __restrict__ h, bf16* __restrict__ m,
                                  bf16* __restrict__ l, int K, int N)
{
    __shared__ float t[32][33];
    const int n0 = blockIdx.x * 32, k0 = blockIdx.y * 32;
    const int tx = threadIdx.x, ty = threadIdx.y;
#pragma unroll
    for (int i = 0; i < 4; i++)
        t[ty + i * 8][tx] = in[(size_t)(k0 + ty + i * 8) * N + n0 + tx];
    __syncthreads();
#pragma unroll
    for (int i = 0; i < 4; i++) {
        const float a = t[tx][ty + i * 8];
        const float ha = __bfloat162float(__float2bfloat16(a));
        const float ra = a - ha;
        const float ma = __bfloat162float(__float2bfloat16(ra));
        const size_t o = (size_t)(n0 + ty + i * 8) * K + k0 + tx;
        h[o] = __float2bfloat16(ha);
        m[o] = __float2bfloat16(ma);
        if (NL == 3) l[o] = __float2bfloat16(ra - ma);
    }
}

// ---------------- gather + STE + commit partials + q limbs ------------------
__global__ void gather_kernel(const float* __restrict__ CB,
                              float* __restrict__ outq,
                              float* __restrict__ outidx,
                              uint2* __restrict__ qh, uint2* __restrict__ qm)
{
    __shared__ float s[128];
    const int n = blockIdx.x;
    const int t = threadIdx.x;
    const int id = g_idx[n];

    float4 z4 = *(const float4*)(g_z + (size_t)n * HRDIM + t * 4);
    float4 q4 = *(const float4*)(CB + (size_t)id * HRDIM + t * 4);

    float4 o;
    o.x = z4.x + (q4.x - z4.x);
    o.y = z4.y + (q4.y - z4.y);
    o.z = z4.z + (q4.z - z4.z);
    o.w = z4.w + (q4.w - z4.w);
    *(float4*)(outq + (size_t)n * HRDIM + t * 4) = o;

    uint32_t h0, m0, l0, h1, m1, l1;
    split_pair(o.x, o.y, h0, m0, l0);
    split_pair(o.z, o.w, h1, m1, l1);
    const size_t qo = (size_t)n * (HRDIM / 4) + t;
    qh[qo] = make_uint2(h0, h1);
    qm[qo] = make_uint2(m0, m1);

    float dx = z4.x - q4.x, dy = z4.y - q4.y, dz = z4.z - q4.z, dw = z4.w - q4.w;
    s[t] = dx * dx + dy * dy + dz * dz + dw * dw;
    __syncthreads();
    for (int off = 64; off > 0; off >>= 1) {
        if (t < off) s[t] += s[t + off];
        __syncthreads();
    }
    if (t == 0) {
        g_part[n] = s[0];
        outidx[n] = (float)id;
    }
}

// ---------------- deterministic commit-loss sum -----------------------------
__global__ void losssum_kernel(float* __restrict__ outloss)
{
    __shared__ float s[1024];
    float acc = 0.f;
    for (int i = threadIdx.x; i < NTOK; i += 1024) acc += g_part[i];
    s[threadIdx.x] = acc;
    __syncthreads();
    for (int off = 512; off > 0; off >>= 1) {
        if (threadIdx.x < off) s[threadIdx.x] += s[threadIdx.x + off];
        __syncthreads();
    }
    if (threadIdx.x == 0)
        outloss[0] = 0.25f * s[0] / (float)((size_t)NTOK * HRDIM);
}

// ---------------- launch ----------------------------------------------------
extern "C" void kernel_launch(void* const* d_in, const int* in_sizes, int n_in,
                              void* d_out, int out_size)
{
    const float* x   = (const float*)d_in[0];
    const float* ew1 = (const float*)d_in[1];
    const float* eb1 = (const float*)d_in[2];
    const float* ew2 = (const float*)d_in[3];
    const float* eb2 = (const float*)d_in[4];
    const float* cb  = (const float*)d_in[5];
    const float* dw1 = (const float*)d_in[6];
    const float* db1 = (const float*)d_in[7];
    const float* dw2 = (const float*)d_in[8];
    const float* db2 = (const float*)d_in[9];

    float* out       = (float*)d_out;
    float* out_recon = out;
    float* out_q     = out + (size_t)NTOK * HDIM;
    float* out_idx   = out_q + (size_t)NTOK * HRDIM;
    float* out_loss  = out_idx + NTOK;

    bf16 *xh, *xm, *xl, *h1h, *h1m, *h1l, *zh, *zm, *zl, *qh, *qm, *h2h, *h2m;
    bf16 *cbh, *cbm, *cbl, *w1h, *w1m, *w1l, *w2h, *w2m, *w2l, *w3h, *w3m, *w4h, *w4m;
    float* z;
    cudaGetSymbolAddress((void**)&xh, g_xh);   cudaGetSymbolAddress((void**)&xm, g_xm);
    cudaGetSymbolAddress((void**)&xl, g_xl);
    cudaGetSymbolAddress((void**)&h1h, g_h1h); cudaGetSymbolAddress((void**)&h1m, g_h1m);
    cudaGetSymbolAddress((void**)&h1l, g_h1l);
    cudaGetSymbolAddress((void**)&zh, g_zh);   cudaGetSymbolAddress((void**)&zm, g_zm);
    cudaGetSymbolAddress((void**)&zl, g_zl);
    cudaGetSymbolAddress((void**)&qh, g_qh);   cudaGetSymbolAddress((void**)&qm, g_qm);
    cudaGetSymbolAddress((void**)&h2h, g_h2h); cudaGetSymbolAddress((void**)&h2m, g_h2m);
    cudaGetSymbolAddress((void**)&cbh, g_cbh); cudaGetSymbolAddress((void**)&cbm, g_cbm);
    cudaGetSymbolAddress((void**)&cbl, g_cbl);
    cudaGetSymbolAddress((void**)&w1h, g_w1h); cudaGetSymbolAddress((void**)&w1m, g_w1m);
    cudaGetSymbolAddress((void**)&w1l, g_w1l);
    cudaGetSymbolAddress((void**)&w2h, g_w2h); cudaGetSymbolAddress((void**)&w2m, g_w2m);
    cudaGetSymbolAddress((void**)&w2l, g_w2l);
    cudaGetSymbolAddress((void**)&w3h, g_w3h); cudaGetSymbolAddress((void**)&w3m, g_w3m);
    cudaGetSymbolAddress((void**)&w4h, g_w4h); cudaGetSymbolAddress((void**)&w4m, g_w4m);
    cudaGetSymbolAddress((void**)&z, g_z);

    cudaFuncSetAttribute(tgemm_kernel<1024, 6, true,  false, 3>, cudaFuncAttributeMaxDynamicSharedMemorySize, SMEM_BYTES);
    cudaFuncSetAttribute(tgemm_kernel<1024, 6, false, true,  3>, cudaFuncAttributeMaxDynamicSharedMemorySize, SMEM_BYTES);
    cudaFuncSetAttribute(tgemm_kernel<512,  3, true,  false, 2>, cudaFuncAttributeMaxDynamicSharedMemorySize, SMEM_BYTES);
    cudaFuncSetAttribute(tgemm_kernel<1024, 3, false, true,  0>, cudaFuncAttributeMaxDynamicSharedMemorySize, SMEM_BYTES);
    cudaFuncSetAttribute(tdist_kernel, cudaFuncAttributeMaxDynamicSharedMemorySize, SMEM_BYTES);

    // prep: split inputs into limb planes (weights transposed+split)
    cbprep_kernel<<<CDIM, 128>>>(cb, (uint2*)cbh, (uint2*)cbm, (uint2*)cbl);
    splitx_kernel<<<(NTOK * HDIM / 4) / 256, 256>>>((const float4*)x, (uint2*)xh, (uint2*)xm, (uint2*)xl);
    dim3 tb(32, 8);
    transsplit_kernel<3><<<dim3(32, 32), tb>>>(ew1, w1h, w1m, w1l, 1024, 1024);
    transsplit_kernel<3><<<dim3(16, 32), tb>>>(ew2, w2h, w2m, w2l, 1024, 512);
    transsplit_kernel<2><<<dim3(32, 16), tb>>>(dw1, w3h, w3m, nullptr, 512, 1024);
    transsplit_kernel<2><<<dim3(32, 32), tb>>>(dw2, w4h, w4m, nullptr, 1024, 1024);

    // encoder (6-pass emulated fp32 on bf16 HMMA), epilogues emit limb planes
    tgemm_kernel<1024, 6, true, false, 3><<<dim3(8, NTOK / 256), 256, SMEM_BYTES>>>(
        xh, xm, xl, w1h, w1m, w1l, eb1, nullptr, h1h, h1m, h1l, HDIM);
    tgemm_kernel<1024, 6, false, true, 3><<<dim3(4, NTOK / 256), 256, SMEM_BYTES>>>(
        h1h, h1m, h1l, w2h, w2m, w2l, eb2, z, zh, zm, zl, HRDIM);

    // nearest codebook entry (6-pass) + combine
    tdist_kernel<<<dim3(NSTRIP, NTOK / 256), 256, SMEM_BYTES>>>(zh, zm, zl, cbh, cbm, cbl);
    combine_kernel<<<NTOK / 256, 256>>>();

    // quantized_st + q limbs + commit partials + indices + loss
    gather_kernel<<<NTOK, 128>>>(cb, out_q, out_idx, (uint2*)qh, (uint2*)qm);
    losssum_kernel<<<1, 1024>>>(out_loss);

    // decoder (3-pass, 2-limb inputs)
    tgemm_kernel<512, 3, true, false, 2><<<dim3(8, NTOK / 256), 256, SMEM_BYTES>>>(
        qh, qm, qm, w3h, w3m, w3m, db1, nullptr, h2h, h2m, nullptr, HDIM);
    tgemm_kernel<1024, 3, false, true, 0><<<dim3(8, NTOK / 256), 256, SMEM_BYTES>>>(
        h2h, h2m, h2m, w4h, w4m, w4m, db2, out_recon, nullptr, nullptr, nullptr, HDIM);
}